// round 10
// baseline (speedup 1.0000x reference)
#include <cuda_runtime.h>
#include <cstdint>

// z = sum_{p,q,r} C[p*9+q*3+r] * u0_p * u1_q * u2_r,  u_i = (1, cos x_i, sin x_i)
//
// Single fused kernel:
//   1. every thread front-batches its 8 input loads (LDG.128, in flight)
//   2. warp 0 builds the 27 trilinear coefficients from q_weights into shared
//      (single-warp, no block barriers inside, ~300 cycles — hidden under the
//      DRAM latency of step 1)
//   3. one __syncthreads, then all 8 warps evaluate from registers+shared.

static constexpr int SPT = 8;
static constexpr int BLOCK = 256;

__global__ void __launch_bounds__(BLOCK) vqc_fused(const float4* __restrict__ in,
                                                   float* __restrict__ out,
                                                   const float* __restrict__ qw,
                                                   int B) {
    __shared__ float cs[27];
    __shared__ float Ure[8][8];
    __shared__ float Uim[8][8];
    __shared__ float Aj[8][8];

    const unsigned FULL = 0xFFFFFFFFu;
    const int t = threadIdx.x;
    const int T = gridDim.x * BLOCK;
    const int g0idx = blockIdx.x * BLOCK + t;

    // ---- 1. Front-batch ALL input loads (independent of coefficients) -----
    float4 x[SPT];
    #pragma unroll
    for (int k = 0; k < SPT; k++) {
        int i = g0idx + k * T;
        i = (i < B) ? i : (B - 1);
        x[k] = in[(size_t)i * 2];        // first 16B of the 32B row
    }

    // ---- 2. Warp 0: build coefficients (other warps go to the barrier) ----
    if (t < 32) {
        const int lane = t;

        // Parallel sincos of all 18 half-angles (lanes 0..17), broadcast later.
        float ang = (lane < 18) ? 0.5f * qw[lane] : 0.f;
        float sh, ch;
        __sincosf(ang, &sh, &ch);

        // Lanes 0..7 simulate basis column j = lane of the fixed unitary.
        const int j = lane & 7;
        float sr[8], si[8];
        #pragma unroll
        for (int m = 0; m < 8; m++) { sr[m] = 0.f; si[m] = 0.f; }
        sr[j] = 1.0f;

        #pragma unroll
        for (int g = 0; g < 9; g++) {        // layer = g/3, qubit = g%3
            const int bit = 4 >> (g % 3);
            float cy = __shfl_sync(FULL, ch, 2 * g);
            float sy = __shfl_sync(FULL, sh, 2 * g);
            float cz = __shfl_sync(FULL, ch, 2 * g + 1);
            float sz = __shfl_sync(FULL, sh, 2 * g + 1);

            // RY
            #pragma unroll
            for (int m = 0; m < 8; m++) {
                if (m & bit) continue;
                int m1 = m | bit;
                float ar = sr[m],  ai = si[m];
                float br = sr[m1], bi = si[m1];
                sr[m]  = cy * ar - sy * br;  si[m]  = cy * ai - sy * bi;
                sr[m1] = sy * ar + cy * br;  si[m1] = sy * ai + cy * bi;
            }
            // RZ
            #pragma unroll
            for (int m = 0; m < 8; m++) {
                float ar = sr[m], ai = si[m];
                if (m & bit) { sr[m] = cz * ar - sz * ai; si[m] = cz * ai + sz * ar; }
                else         { sr[m] = cz * ar + sz * ai; si[m] = cz * ai - sz * ar; }
            }
            // End of layer: CNOT01 then CNOT12
            if (g % 3 == 2) {
                #pragma unroll
                for (int m = 4; m < 6; m++) {    // swap (4,6),(5,7)
                    int m1 = m | 2; float tmp;
                    tmp = sr[m]; sr[m] = sr[m1]; sr[m1] = tmp;
                    tmp = si[m]; si[m] = si[m1]; si[m1] = tmp;
                }
                #pragma unroll
                for (int m = 2; m < 8; m += 4) { // swap (2,3),(6,7)
                    int m1 = m | 1; float tmp;
                    tmp = sr[m]; sr[m] = sr[m1]; sr[m1] = tmp;
                    tmp = si[m]; si[m] = si[m1]; si[m1] = tmp;
                }
            }
        }

        if (lane < 8) {
            #pragma unroll
            for (int m = 0; m < 8; m++) { Ure[m][j] = sr[m]; Uim[m][j] = si[m]; }
        }
        __syncwarp();

        // A[j][k] = sum_m sign(m)(Ure[m][j]Ure[m][k] + Uim[m][j]Uim[m][k])
        #pragma unroll
        for (int h = 0; h < 2; h++) {
            int e = lane + h * 32;
            int jj = e >> 3, kk = e & 7;
            float a = 0.f;
            #pragma unroll
            for (int m = 0; m < 8; m++) {
                float sgn = (m & 4) ? -1.f : 1.f;
                a += sgn * (Ure[m][jj] * Ure[m][kk] + Uim[m][jj] * Uim[m][kk]);
            }
            Aj[jj][kk] = a;
        }
        __syncwarp();

        // Contraction to 27 coefficients: 2 rank-1 updates per lane, then
        // 5-level warp tree reduction.
        float cpart[27];
        #pragma unroll
        for (int i = 0; i < 27; i++) cpart[i] = 0.f;

        #pragma unroll
        for (int h = 0; h < 2; h++) {
            int e = lane + h * 32;
            int jj = e >> 3, kk = e & 7;
            float a = Aj[jj][kk];

            float ga[3], gb[3], gc[3];
            {
                int aa = (jj >> 2) & 1, bb = (kk >> 2) & 1;
                ga[0] = (aa == bb) ? 0.5f : 0.f;
                ga[1] = (aa == bb) ? (aa ? -0.5f : 0.5f) : 0.f;
                ga[2] = (aa != bb) ? 0.5f : 0.f;
            }
            {
                int aa = (jj >> 1) & 1, bb = (kk >> 1) & 1;
                gb[0] = (aa == bb) ? 0.5f : 0.f;
                gb[1] = (aa == bb) ? (aa ? -0.5f : 0.5f) : 0.f;
                gb[2] = (aa != bb) ? 0.5f : 0.f;
            }
            {
                int aa = jj & 1, bb = kk & 1;
                gc[0] = (aa == bb) ? 0.5f : 0.f;
                gc[1] = (aa == bb) ? (aa ? -0.5f : 0.5f) : 0.f;
                gc[2] = (aa != bb) ? 0.5f : 0.f;
            }

            #pragma unroll
            for (int p = 0; p < 3; p++) {
                float a0 = a * ga[p];
                #pragma unroll
                for (int q = 0; q < 3; q++) {
                    float a01 = a0 * gb[q];
                    #pragma unroll
                    for (int r = 0; r < 3; r++)
                        cpart[p * 9 + q * 3 + r] =
                            fmaf(a01, gc[r], cpart[p * 9 + q * 3 + r]);
                }
            }
        }

        #pragma unroll
        for (int off = 16; off > 0; off >>= 1) {
            #pragma unroll
            for (int i = 0; i < 27; i++)
                cpart[i] += __shfl_xor_sync(FULL, cpart[i], off);
        }
        if (lane < 27) cs[lane] = cpart[lane];
    }

    __syncthreads();   // cs ready; loads have been in flight the whole time

    // ---- 3. Evaluate SPT samples per thread --------------------------------
    #pragma unroll
    for (int k = 0; k < SPT; k++) {
        float C0, S0, C1, S1, C2, S2;
        __sincosf(x[k].x, &S0, &C0);
        __sincosf(x[k].y, &S1, &C1);
        __sincosf(x[k].z, &S2, &C2);

        float u0[3] = {1.f, C0, S0};
        float u1[3] = {1.f, C1, S1};
        float z = 0.f;
        #pragma unroll
        for (int p = 0; p < 3; p++) {
            #pragma unroll
            for (int q = 0; q < 3; q++) {
                const float* c3 = &cs[p * 9 + q * 3];
                float w = c3[0];
                w = fmaf(c3[1], C2, w);
                w = fmaf(c3[2], S2, w);
                z = fmaf(u0[p] * u1[q], w, z);
            }
        }
        int i = g0idx + k * T;
        if (i < B) out[i] = z;
    }
}

extern "C" void kernel_launch(void* const* d_in, const int* in_sizes, int n_in,
                              void* d_out, int out_size) {
    const float* inputs = (const float*)d_in[0];   // (B, 8) float32
    const float* qw     = (const float*)d_in[1];   // (3, 3, 2) float32
    float* out          = (float*)d_out;           // (B, 1) float32

    int B = in_sizes[0] / 8;
    int grid = (B + BLOCK * SPT - 1) / (BLOCK * SPT);   // 512 for B = 2^20

    vqc_fused<<<grid, BLOCK>>>((const float4*)inputs, out, qw, B);
}